// round 1
// baseline (speedup 1.0000x reference)
#include <cuda_runtime.h>

// Problem constants (HybridODENN): B=1024, T=256, H=128, NL=4 (3 hidden), S=6
#define B_DIM 1024
#define T_DIM 256
#define H_DIM 128
#define S_DIM 6
#define ROWS 8
#define GRID (B_DIM / ROWS)      // 128 CTAs, one per SM (smem-limited)
#define NTHREADS 256

// ODE constants
#define C_A_GI 0.01f
#define C_K_I  0.1f
#define C_RHO  0.05f
#define C_EMAX 2.0f
#define C_EC50 5.0f
#define C_VMAX 1.0f
#define C_KM   100.0f
#define C_KL   0.2f

struct __align__(16) Smem {
    float W_h[3][H_DIM][H_DIM];   // 192 KB  [layer][k][j]
    float W_in[9][H_DIM];         // 4.5 KB  [i][j]
    float W_out_t[S_DIM][H_DIM];  // 3 KB    transposed: [o][k]
    float b_in[H_DIM];
    float b_h[3][H_DIM];
    float b_out[8];
    float h[2][ROWS][H_DIM];      // ping-pong activations (8 KB)
    float y[ROWS][S_DIM];         // state at step start
    float ycur[ROWS][S_DIM];      // current stage argument
    float acc[ROWS][S_DIM];       // RK accumulator (starts = y)
    float mv[2][3][ROWS];         // [meal/tvns][t0/tm/t1][row]
    float tst[4];                 // stage times
    float wgt[4];                 // RK weights dt/6,dt/3,dt/3,dt/6
    float cnx[4];                 // next-stage y-perturbation coeff
};

__device__ __forceinline__ float ode_comp(int o, const float* y, float m) {
    float G = y[0], I = y[1], N = y[2], L = y[3], GE = y[4], F = y[5];
    switch (o) {
        case 0: return -C_A_GI * I * G + C_RHO * GE;
        case 1: return C_VMAX * G / (C_KM + G) * (1.0f + C_EMAX * L / (C_EC50 + L)) - C_K_I * I;
        case 2: return -C_RHO * N;
        case 3: return C_RHO * GE - C_KL * L;
        case 4: return m - C_RHO * GE;
        default: return -C_A_GI * I * F;
    }
}

__global__ void __launch_bounds__(NTHREADS, 1)
hybrid_ode_kernel(const float* __restrict__ init,
                  const float* __restrict__ t_span,
                  const float* __restrict__ meal,
                  const float* __restrict__ tvns,
                  const float* __restrict__ gW_in,
                  const float* __restrict__ gb_in,
                  const float* __restrict__ gW_h,
                  const float* __restrict__ gb_h,
                  const float* __restrict__ gW_out,
                  const float* __restrict__ gb_out,
                  float* __restrict__ out)
{
    extern __shared__ __align__(16) char smem_raw[];
    Smem* s = reinterpret_cast<Smem*>(smem_raw);

    const int tid  = threadIdx.x;
    const int base = blockIdx.x * ROWS;

    // ---- one-time weight staging into SMEM ----
    {
        float4* dst = reinterpret_cast<float4*>(&s->W_h[0][0][0]);
        const float4* src = reinterpret_cast<const float4*>(gW_h);
        const int n4 = 3 * H_DIM * H_DIM / 4;
        for (int i = tid; i < n4; i += NTHREADS) dst[i] = src[i];
    }
    for (int i = tid; i < 9 * H_DIM; i += NTHREADS) (&s->W_in[0][0])[i] = gW_in[i];
    for (int i = tid; i < H_DIM; i += NTHREADS) s->b_in[i] = gb_in[i];
    for (int i = tid; i < 3 * H_DIM; i += NTHREADS) (&s->b_h[0][0])[i] = gb_h[i];
    for (int i = tid; i < H_DIM * S_DIM; i += NTHREADS) {
        int k = i / S_DIM, o = i % S_DIM;
        s->W_out_t[o][k] = gW_out[i];
    }
    if (tid < S_DIM) s->b_out[tid] = gb_out[tid];
    if (tid < ROWS * S_DIM) {
        int r = tid / S_DIM, o = tid % S_DIM;
        float v = init[(base + r) * S_DIM + o];
        s->y[r][o] = v; s->ycur[r][o] = v; s->acc[r][o] = v;
        out[(size_t)(base + r) * T_DIM * S_DIM + o] = v;   // trajectory[t=0]
    }
    __syncthreads();

    // GEMM micro-tile mapping: 2 rows x 2 cols per thread
    const int cp = tid & 63;        // column pair index -> cols 2cp, 2cp+1
    const int rp = tid >> 6;        // row pair index    -> rows 2rp, 2rp+1
    const int r0 = rp * 2, r1 = rp * 2 + 1;
    const int c0 = cp * 2;
    const int w = tid >> 5, lane = tid & 31;  // warp w owns batch row w in epilogue

    for (int t = 0; t < T_DIM - 1; ++t) {
        // ---- per-step setup ----
        if (tid == 0) {
            float T0 = t_span[t], T1 = t_span[t + 1];
            float dt = T1 - T0;
            float tm = T0 + 0.5f * dt;
            s->tst[0] = T0; s->tst[1] = tm; s->tst[2] = tm; s->tst[3] = T1;
            float w14 = dt * (1.0f / 6.0f), w23 = dt * (1.0f / 3.0f);
            s->wgt[0] = w14; s->wgt[1] = w23; s->wgt[2] = w23; s->wgt[3] = w14;
            s->cnx[0] = 0.5f * dt; s->cnx[1] = 0.5f * dt; s->cnx[2] = dt; s->cnx[3] = 0.0f;
        }
        if (tid < ROWS) {
            size_t ri = (size_t)(base + tid) * T_DIM + t;
            float M0 = meal[ri], M1 = meal[ri + 1];
            float V0 = tvns[ri], V1 = tvns[ri + 1];
            s->mv[0][0][tid] = M0; s->mv[0][1][tid] = 0.5f * (M0 + M1); s->mv[0][2][tid] = M1;
            s->mv[1][0][tid] = V0; s->mv[1][1][tid] = 0.5f * (V0 + V1); s->mv[1][2][tid] = V1;
        }
        __syncthreads();

        #pragma unroll 1
        for (int st = 0; st < 4; ++st) {
            const int ph = (st + 1) >> 1;            // 0,1,1,2
            const float ts = s->tst[st];
            const float* ms = s->mv[0][ph];
            const float* vs = s->mv[1][ph];

            // ---- input layer: x = [t, y(6), y3, v] -> h[0] ----
            #pragma unroll
            for (int it = 0; it < (ROWS * H_DIM) / NTHREADS; ++it) {
                int idx = tid + it * NTHREADS;
                int r = idx >> 7, j = idx & (H_DIM - 1);
                const float* yr = s->ycur[r];
                float a = s->b_in[j]
                        + ts    * s->W_in[0][j]
                        + yr[0] * s->W_in[1][j]
                        + yr[1] * s->W_in[2][j]
                        + yr[2] * s->W_in[3][j]
                        + yr[3] * s->W_in[4][j]
                        + yr[4] * s->W_in[5][j]
                        + yr[5] * s->W_in[6][j]
                        + yr[3] * s->W_in[7][j]
                        + vs[r] * s->W_in[8][j];
                s->h[0][r][j] = tanhf(a);
            }
            __syncthreads();

            // ---- 3 hidden layers: h := tanh(h @ W_h[L] + b_h[L]) ----
            #pragma unroll 1
            for (int L = 0; L < 3; ++L) {
                const float* hin  = &s->h[L & 1][0][0];
                float*       hout = &s->h[(L & 1) ^ 1][0][0];
                const float* Wl   = &s->W_h[L][0][0];
                float b0 = s->b_h[L][c0], b1 = s->b_h[L][c0 + 1];
                float a00 = b0, a01 = b1, a10 = b0, a11 = b1;
                #pragma unroll 4
                for (int k = 0; k < H_DIM; k += 4) {
                    float4 ha = *reinterpret_cast<const float4*>(&hin[r0 * H_DIM + k]);
                    float4 hb = *reinterpret_cast<const float4*>(&hin[r1 * H_DIM + k]);
                    float2 w0 = *reinterpret_cast<const float2*>(&Wl[(k + 0) * H_DIM + c0]);
                    float2 w1 = *reinterpret_cast<const float2*>(&Wl[(k + 1) * H_DIM + c0]);
                    float2 w2 = *reinterpret_cast<const float2*>(&Wl[(k + 2) * H_DIM + c0]);
                    float2 w3 = *reinterpret_cast<const float2*>(&Wl[(k + 3) * H_DIM + c0]);
                    a00 += ha.x * w0.x; a01 += ha.x * w0.y; a10 += hb.x * w0.x; a11 += hb.x * w0.y;
                    a00 += ha.y * w1.x; a01 += ha.y * w1.y; a10 += hb.y * w1.x; a11 += hb.y * w1.y;
                    a00 += ha.z * w2.x; a01 += ha.z * w2.y; a10 += hb.z * w2.x; a11 += hb.z * w2.y;
                    a00 += ha.w * w3.x; a01 += ha.w * w3.y; a10 += hb.w * w3.x; a11 += hb.w * w3.y;
                }
                float2 o0 = make_float2(tanhf(a00), tanhf(a01));
                float2 o1 = make_float2(tanhf(a10), tanhf(a11));
                *reinterpret_cast<float2*>(&hout[r0 * H_DIM + c0]) = o0;
                *reinterpret_cast<float2*>(&hout[r1 * H_DIM + c0]) = o1;
                __syncthreads();
            }

            // ---- output layer (warp-reduced dots) + ODE core + RK bookkeeping ----
            {
                const float* hr = &s->h[1][w][0];   // after L=2, result lives in h[1]
                float dots[S_DIM];
                #pragma unroll
                for (int o = 0; o < S_DIM; ++o) {
                    float p = hr[lane]      * s->W_out_t[o][lane]
                            + hr[lane + 32] * s->W_out_t[o][lane + 32]
                            + hr[lane + 64] * s->W_out_t[o][lane + 64]
                            + hr[lane + 96] * s->W_out_t[o][lane + 96];
                    #pragma unroll
                    for (int off = 16; off; off >>= 1)
                        p += __shfl_xor_sync(0xffffffffu, p, off);
                    dots[o] = p;
                }
                if (lane == 0) {
                    float yc[S_DIM];
                    #pragma unroll
                    for (int o = 0; o < S_DIM; ++o) yc[o] = s->ycur[w][o];
                    float m   = ms[w];
                    float wg  = s->wgt[st];
                    float cn  = s->cnx[st];
                    #pragma unroll
                    for (int o = 0; o < S_DIM; ++o) {
                        float kv = dots[o] + s->b_out[o] + ode_comp(o, yc, m);
                        float a  = s->acc[w][o] + wg * kv;
                        s->acc[w][o] = a;
                        if (st < 3) {
                            s->ycur[w][o] = s->y[w][o] + cn * kv;
                        } else {
                            s->ycur[w][o] = a;     // stage-0 argument of next step
                            s->y[w][o]    = a;     // new state (acc already = new y)
                            out[(size_t)(base + w) * T_DIM * S_DIM
                                + (size_t)(t + 1) * S_DIM + o] = a;
                        }
                    }
                }
            }
            __syncthreads();
        } // stages
    } // time steps
}

extern "C" void kernel_launch(void* const* d_in, const int* in_sizes, int n_in,
                              void* d_out, int out_size) {
    const float* init   = (const float*)d_in[0];
    const float* t_span = (const float*)d_in[1];
    const float* meal   = (const float*)d_in[2];
    const float* tvns   = (const float*)d_in[3];
    const float* W_in   = (const float*)d_in[4];
    const float* b_in   = (const float*)d_in[5];
    const float* W_h    = (const float*)d_in[6];
    const float* b_h    = (const float*)d_in[7];
    const float* W_out  = (const float*)d_in[8];
    const float* b_out  = (const float*)d_in[9];
    float* out = (float*)d_out;

    const size_t smem_bytes = sizeof(Smem);  // ~215 KB, needs opt-in
    cudaFuncSetAttribute(hybrid_ode_kernel,
                         cudaFuncAttributeMaxDynamicSharedMemorySize,
                         (int)smem_bytes);

    hybrid_ode_kernel<<<GRID, NTHREADS, smem_bytes>>>(
        init, t_span, meal, tvns, W_in, b_in, W_h, b_h, W_out, b_out, out);
}

// round 2
// speedup vs baseline: 1.0293x; 1.0293x over previous
#include <cuda_runtime.h>

// Problem constants (HybridODENN): B=1024, T=256, H=128, NL=4 (3 hidden), S=6
#define B_DIM 1024
#define T_DIM 256
#define H_DIM 128
#define S_DIM 6
#define ROWS 8
#define GRID (B_DIM / ROWS)      // 128 CTAs, one per SM (smem-limited)
#define NTHREADS 512

// ODE constants
#define C_A_GI 0.01f
#define C_K_I  0.1f
#define C_RHO  0.05f
#define C_EMAX 2.0f
#define C_EC50 5.0f
#define C_VMAX 1.0f
#define C_KM   100.0f
#define C_KL   0.2f

// Packed fp32x2 FMA (Blackwell): d.lo += a.lo*b.lo ; d.hi += a.hi*b.hi (IEEE fp32 each lane)
#define FFMA2(d, a, b) asm("fma.rn.f32x2 %0, %1, %2, %0;" : "+l"(d) : "l"(a), "l"(b))

__device__ __forceinline__ float2 unpack2(unsigned long long v) {
    float lo, hi;
    asm("mov.b64 {%0, %1}, %2;" : "=f"(lo), "=f"(hi) : "l"(v));
    return make_float2(lo, hi);
}

struct __align__(16) Smem {
    // W_h repacked: [layer][kpair(64)][col(128)][2]  -> elem (l,k,c) at l*16384 + (k>>1)*256 + c*2 + (k&1)
    float W_h[3][64][256];        // 192 KB
    float W_in[9][H_DIM];         // 4.5 KB
    float W_out_t[S_DIM][H_DIM];  // 3 KB (transposed [o][k])
    float b_in[H_DIM];
    float b_h[3][H_DIM];
    float b_out[8];
    float h[2][ROWS][H_DIM];      // ping-pong activations (4 KB each)
    float P[ROWS * H_DIM];        // split-K partials from team 1 (4 KB)
    float y[ROWS][S_DIM];
    float ycur[ROWS][S_DIM];
    float acc[ROWS][S_DIM];
    float mv[2][3][ROWS];         // [meal/tvns][t0/tm/t1][row]
    float tst[4];
    float wgt[4];
    float cnx[4];
};

__device__ __forceinline__ float ode_comp(int o, const float* y, float m) {
    float G = y[0], I = y[1], N = y[2], L = y[3], GE = y[4], F = y[5];
    switch (o) {
        case 0: return -C_A_GI * I * G + C_RHO * GE;
        case 1: return C_VMAX * G / (C_KM + G) * (1.0f + C_EMAX * L / (C_EC50 + L)) - C_K_I * I;
        case 2: return -C_RHO * N;
        case 3: return C_RHO * GE - C_KL * L;
        case 4: return m - C_RHO * GE;
        default: return -C_A_GI * I * F;
    }
}

__global__ void __launch_bounds__(NTHREADS, 1)
hybrid_ode_kernel(const float* __restrict__ init,
                  const float* __restrict__ t_span,
                  const float* __restrict__ meal,
                  const float* __restrict__ tvns,
                  const float* __restrict__ gW_in,
                  const float* __restrict__ gb_in,
                  const float* __restrict__ gW_h,
                  const float* __restrict__ gb_h,
                  const float* __restrict__ gW_out,
                  const float* __restrict__ gb_out,
                  float* __restrict__ out)
{
    extern __shared__ __align__(16) char smem_raw[];
    Smem* s = reinterpret_cast<Smem*>(smem_raw);

    const int tid  = threadIdx.x;
    const int base = blockIdx.x * ROWS;

    // ---- one-time weight staging (W_h repacked for k-pair f32x2 layout) ----
    for (int i = tid; i < 3 * H_DIM * H_DIM; i += NTHREADS) {
        int l = i >> 14;                // /16384
        int rem = i & 16383;
        int k = rem >> 7, c = rem & 127;
        (&s->W_h[0][0][0])[l * 16384 + (k >> 1) * 256 + c * 2 + (k & 1)] = gW_h[i];
    }
    for (int i = tid; i < 9 * H_DIM; i += NTHREADS) (&s->W_in[0][0])[i] = gW_in[i];
    for (int i = tid; i < H_DIM; i += NTHREADS) s->b_in[i] = gb_in[i];
    for (int i = tid; i < 3 * H_DIM; i += NTHREADS) (&s->b_h[0][0])[i] = gb_h[i];
    for (int i = tid; i < H_DIM * S_DIM; i += NTHREADS) {
        int k = i / S_DIM, o = i % S_DIM;
        s->W_out_t[o][k] = gW_out[i];
    }
    if (tid < S_DIM) s->b_out[tid] = gb_out[tid];
    if (tid < ROWS * S_DIM) {
        int r = tid / S_DIM, o = tid % S_DIM;
        float v = init[(base + r) * S_DIM + o];
        s->y[r][o] = v; s->ycur[r][o] = v; s->acc[r][o] = v;
        out[(size_t)(base + r) * T_DIM * S_DIM + o] = v;   // trajectory[t=0]
    }
    __syncthreads();

    // GEMM mapping: 2 teams (split-K) x 256 threads; each thread = 2 rows x 2 cols
    const int team  = tid >> 8;          // 0: k 0..63, 1: k 64..127
    const int tt    = tid & 255;
    const int rg    = tt >> 6;           // 0..3 -> rows 2rg, 2rg+1
    const int r0    = rg * 2, r1 = rg * 2 + 1;
    const int c0    = (tt & 63) * 2;     // cols c0, c0+1
    const int pbase = team * 32;         // k-pair base
    const int w = tid >> 5, lane = tid & 31;  // epilogue: warp w (<8) owns batch row w

    for (int t = 0; t < T_DIM - 1; ++t) {
        // ---- per-step setup ----
        if (tid == 0) {
            float T0 = t_span[t], T1 = t_span[t + 1];
            float dt = T1 - T0;
            float tm = T0 + 0.5f * dt;
            s->tst[0] = T0; s->tst[1] = tm; s->tst[2] = tm; s->tst[3] = T1;
            float w14 = dt * (1.0f / 6.0f), w23 = dt * (1.0f / 3.0f);
            s->wgt[0] = w14; s->wgt[1] = w23; s->wgt[2] = w23; s->wgt[3] = w14;
            s->cnx[0] = 0.5f * dt; s->cnx[1] = 0.5f * dt; s->cnx[2] = dt; s->cnx[3] = 0.0f;
        }
        if (tid < ROWS) {
            size_t ri = (size_t)(base + tid) * T_DIM + t;
            float M0 = meal[ri], M1 = meal[ri + 1];
            float V0 = tvns[ri], V1 = tvns[ri + 1];
            s->mv[0][0][tid] = M0; s->mv[0][1][tid] = 0.5f * (M0 + M1); s->mv[0][2][tid] = M1;
            s->mv[1][0][tid] = V0; s->mv[1][1][tid] = 0.5f * (V0 + V1); s->mv[1][2][tid] = V1;
        }
        __syncthreads();

        #pragma unroll 1
        for (int st = 0; st < 4; ++st) {
            const int ph = (st + 1) >> 1;            // 0,1,1,2
            const float ts = s->tst[st];
            const float* ms = s->mv[0][ph];
            const float* vs = s->mv[1][ph];

            // ---- input layer: x = [t, y(6), y3, v] -> h[0] (2 outputs/thread) ----
            #pragma unroll
            for (int it = 0; it < (ROWS * H_DIM) / NTHREADS; ++it) {
                int idx = tid + it * NTHREADS;
                int r = idx >> 7, j = idx & (H_DIM - 1);
                const float* yr = s->ycur[r];
                float a = s->b_in[j]
                        + ts    * s->W_in[0][j]
                        + yr[0] * s->W_in[1][j]
                        + yr[1] * s->W_in[2][j]
                        + yr[2] * s->W_in[3][j]
                        + yr[3] * s->W_in[4][j]
                        + yr[4] * s->W_in[5][j]
                        + yr[5] * s->W_in[6][j]
                        + yr[3] * s->W_in[7][j]
                        + vs[r] * s->W_in[8][j];
                s->h[0][r][j] = tanhf(a);
            }
            __syncthreads();

            // ---- 3 hidden layers: split-K f32x2 GEMM + combine ----
            #pragma unroll 1
            for (int L = 0; L < 3; ++L) {
                const float* hin  = &s->h[L & 1][0][0];
                float*       hout = &s->h[(L & 1) ^ 1][0][0];
                const float* Wp   = &s->W_h[L][0][0];

                unsigned long long a00 = 0, a01 = 0, a10 = 0, a11 = 0;
                #pragma unroll
                for (int p = 0; p < 32; p += 2) {
                    int pp = pbase + p;
                    ulonglong2 hA = *reinterpret_cast<const ulonglong2*>(&hin[r0 * H_DIM + pp * 2]);
                    ulonglong2 hB = *reinterpret_cast<const ulonglong2*>(&hin[r1 * H_DIM + pp * 2]);
                    ulonglong2 w0 = *reinterpret_cast<const ulonglong2*>(&Wp[pp * 256 + c0 * 2]);
                    ulonglong2 w1 = *reinterpret_cast<const ulonglong2*>(&Wp[(pp + 1) * 256 + c0 * 2]);
                    FFMA2(a00, hA.x, w0.x); FFMA2(a01, hA.x, w0.y);
                    FFMA2(a10, hB.x, w0.x); FFMA2(a11, hB.x, w0.y);
                    FFMA2(a00, hA.y, w1.x); FFMA2(a01, hA.y, w1.y);
                    FFMA2(a10, hB.y, w1.x); FFMA2(a11, hB.y, w1.y);
                }
                float2 s00 = unpack2(a00), s01 = unpack2(a01);
                float2 s10 = unpack2(a10), s11 = unpack2(a11);
                float p00 = s00.x + s00.y, p01 = s01.x + s01.y;
                float p10 = s10.x + s10.y, p11 = s11.x + s11.y;
                float* dst = team ? s->P : hout;   // team0 -> hout, team1 -> P
                *reinterpret_cast<float2*>(&dst[r0 * H_DIM + c0]) = make_float2(p00, p01);
                *reinterpret_cast<float2*>(&dst[r1 * H_DIM + c0]) = make_float2(p10, p11);
                __syncthreads();

                // combine: 1024 outputs, 2 per thread (vectorized)
                {
                    float2 pA = *reinterpret_cast<const float2*>(&hout[tid * 2]);
                    float2 pB = *reinterpret_cast<const float2*>(&s->P[tid * 2]);
                    int col = (tid * 2) & (H_DIM - 1);
                    float2 bb = *reinterpret_cast<const float2*>(&s->b_h[L][col]);
                    float2 rr;
                    rr.x = tanhf(pA.x + pB.x + bb.x);
                    rr.y = tanhf(pA.y + pB.y + bb.y);
                    *reinterpret_cast<float2*>(&hout[tid * 2]) = rr;
                }
                __syncthreads();
            }

            // ---- output layer (warp-reduced dots) + ODE core + RK bookkeeping ----
            if (w < ROWS) {
                const float* hr = &s->h[1][w][0];   // after L=2, result in h[1]
                float dots[S_DIM];
                #pragma unroll
                for (int o = 0; o < S_DIM; ++o) {
                    float p = hr[lane]      * s->W_out_t[o][lane]
                            + hr[lane + 32] * s->W_out_t[o][lane + 32]
                            + hr[lane + 64] * s->W_out_t[o][lane + 64]
                            + hr[lane + 96] * s->W_out_t[o][lane + 96];
                    #pragma unroll
                    for (int off = 16; off; off >>= 1)
                        p += __shfl_xor_sync(0xffffffffu, p, off);
                    dots[o] = p;
                }
                if (lane == 0) {
                    float yc[S_DIM];
                    #pragma unroll
                    for (int o = 0; o < S_DIM; ++o) yc[o] = s->ycur[w][o];
                    float m   = ms[w];
                    float wg  = s->wgt[st];
                    float cn  = s->cnx[st];
                    #pragma unroll
                    for (int o = 0; o < S_DIM; ++o) {
                        float kv = dots[o] + s->b_out[o] + ode_comp(o, yc, m);
                        float a  = s->acc[w][o] + wg * kv;
                        s->acc[w][o] = a;
                        if (st < 3) {
                            s->ycur[w][o] = s->y[w][o] + cn * kv;
                        } else {
                            s->ycur[w][o] = a;
                            s->y[w][o]    = a;
                            out[(size_t)(base + w) * T_DIM * S_DIM
                                + (size_t)(t + 1) * S_DIM + o] = a;
                        }
                    }
                }
            }
            __syncthreads();
        } // stages
    } // time steps
}

extern "C" void kernel_launch(void* const* d_in, const int* in_sizes, int n_in,
                              void* d_out, int out_size) {
    const float* init   = (const float*)d_in[0];
    const float* t_span = (const float*)d_in[1];
    const float* meal   = (const float*)d_in[2];
    const float* tvns   = (const float*)d_in[3];
    const float* W_in   = (const float*)d_in[4];
    const float* b_in   = (const float*)d_in[5];
    const float* W_h    = (const float*)d_in[6];
    const float* b_h    = (const float*)d_in[7];
    const float* W_out  = (const float*)d_in[8];
    const float* b_out  = (const float*)d_in[9];
    float* out = (float*)d_out;

    const size_t smem_bytes = sizeof(Smem);  // ~220 KB, needs opt-in
    cudaFuncSetAttribute(hybrid_ode_kernel,
                         cudaFuncAttributeMaxDynamicSharedMemorySize,
                         (int)smem_bytes);

    hybrid_ode_kernel<<<GRID, NTHREADS, smem_bytes>>>(
        init, t_span, meal, tvns, W_in, b_in, W_h, b_h, W_out, b_out, out);
}

// round 3
// speedup vs baseline: 1.2495x; 1.2140x over previous
#include <cuda_runtime.h>

// HybridODENN: B=1024, T=256, H=128, 3 hidden layers, S=6
#define B_DIM 1024
#define T_DIM 256
#define H_DIM 128
#define S_DIM 6
#define ROWS 8
#define GRID (B_DIM / ROWS)      // 128 CTAs
#define NTHREADS 512

// ODE constants
#define C_A_GI 0.01f
#define C_K_I  0.1f
#define C_RHO  0.05f
#define C_EMAX 2.0f
#define C_EC50 5.0f
#define C_VMAX 1.0f
#define C_KM   100.0f
#define C_KL   0.2f

// h column swizzle: XOR bits 2-3 with bits 5-6 (stays within 16-float kl-group)
#define HSWZ(c) ((c) ^ (((c) >> 3) & 12))

#define WPAD 272                  // 256 + 16 floats: odd/even kl -> complementary 64B halves

typedef unsigned long long ull;

#define FFMA2(d, a, b) asm("fma.rn.f32x2 %0, %1, %2, %0;" : "+l"(d) : "l"(a), "l"(b))

__device__ __forceinline__ ull add2(ull a, ull b) {
    ull d; asm("add.rn.f32x2 %0, %1, %2;" : "=l"(d) : "l"(a), "l"(b)); return d;
}
__device__ __forceinline__ float2 unpack2(ull v) {
    float lo, hi;
    asm("mov.b64 {%0, %1}, %2;" : "=f"(lo), "=f"(hi) : "l"(v));
    return make_float2(lo, hi);
}

struct __align__(16) Smem {
    // W_h[L][j][kl][c2]: elem (k,c) -> kp=k>>1, j=kp&7, kl=kp>>3, c2=c*2+(k&1)
    float W_h[3][8][8][WPAD];     // ~204 KB
    float W_in[9][H_DIM];
    float W_out_t[S_DIM][H_DIM];
    float b_in[H_DIM];
    float b_h[3][H_DIM];
    float b_out[8];
    float h[2][ROWS][H_DIM];      // swizzled columns (HSWZ)
    float y[ROWS][S_DIM];
    float ycur[ROWS][S_DIM];
    float acc[ROWS][S_DIM];
    float mv[2][3][ROWS];
    float tst[4];
    float wgt[4];
    float cnx[4];
};

__device__ __forceinline__ float ode_comp(int o, const float* y, float m) {
    float G = y[0], I = y[1], N = y[2], L = y[3], GE = y[4], F = y[5];
    switch (o) {
        case 0: return -C_A_GI * I * G + C_RHO * GE;
        case 1: return C_VMAX * G / (C_KM + G) * (1.0f + C_EMAX * L / (C_EC50 + L)) - C_K_I * I;
        case 2: return -C_RHO * N;
        case 3: return C_RHO * GE - C_KL * L;
        case 4: return m - C_RHO * GE;
        default: return -C_A_GI * I * F;
    }
}

__global__ void __launch_bounds__(NTHREADS, 1)
hybrid_ode_kernel(const float* __restrict__ init,
                  const float* __restrict__ t_span,
                  const float* __restrict__ meal,
                  const float* __restrict__ tvns,
                  const float* __restrict__ gW_in,
                  const float* __restrict__ gb_in,
                  const float* __restrict__ gW_h,
                  const float* __restrict__ gb_h,
                  const float* __restrict__ gW_out,
                  const float* __restrict__ gb_out,
                  float* __restrict__ out)
{
    extern __shared__ __align__(16) char smem_raw[];
    Smem* s = reinterpret_cast<Smem*>(smem_raw);

    const int tid  = threadIdx.x;
    const int base = blockIdx.x * ROWS;

    // ---- one-time weight staging ----
    for (int i = tid; i < 3 * H_DIM * H_DIM; i += NTHREADS) {
        int l = i >> 14;
        int rem = i & 16383;
        int k = rem >> 7, c = rem & 127;
        int kp = k >> 1;
        s->W_h[l][kp & 7][kp >> 3][c * 2 + (k & 1)] = gW_h[i];
    }
    for (int i = tid; i < 9 * H_DIM; i += NTHREADS) (&s->W_in[0][0])[i] = gW_in[i];
    for (int i = tid; i < H_DIM; i += NTHREADS) s->b_in[i] = gb_in[i];
    for (int i = tid; i < 3 * H_DIM; i += NTHREADS) (&s->b_h[0][0])[i] = gb_h[i];
    for (int i = tid; i < H_DIM * S_DIM; i += NTHREADS) {
        int k = i / S_DIM, o = i % S_DIM;
        s->W_out_t[o][k] = gW_out[i];
    }
    if (tid < S_DIM) s->b_out[tid] = gb_out[tid];
    if (tid < ROWS * S_DIM) {
        int r = tid / S_DIM, o = tid % S_DIM;
        float v = init[(base + r) * S_DIM + o];
        s->y[r][o] = v; s->ycur[r][o] = v; s->acc[r][o] = v;
        out[(size_t)(base + r) * T_DIM * S_DIM + o] = v;
    }
    __syncthreads();

    // ---- warp-tile GEMM mapping ----
    const int w    = tid >> 5;          // warp 0..15 -> cols [w*8, w*8+8)
    const int lane = tid & 31;
    const int cl   = lane & 3;          // 2 cols per lane
    const int kl   = lane >> 2;         // k-slice [kl*16, kl*16+16)
    const int c0   = w * 8 + cl * 2;
    // W float offset within layer for chunk j2 (kpair j=2*j2): j*2176 + kl*WPAD + c0*2
    const int wofs = kl * WPAD + c0 * 2;
    // h read offsets (swizzled col) per chunk
    int hc[4];
    #pragma unroll
    for (int j2 = 0; j2 < 4; ++j2) hc[j2] = HSWZ(kl * 16 + 4 * j2);
    // epilogue swizzled indices
    const int sw0 = HSWZ(lane), sw1 = HSWZ(lane + 32), sw2 = HSWZ(lane + 64), sw3 = HSWZ(lane + 96);
    const bool hi1 = (lane & 16) != 0;
    const bool hi2 = (lane & 8)  != 0;
    const bool hi3 = (lane & 4)  != 0;

    for (int t = 0; t < T_DIM - 1; ++t) {
        if (tid == 0) {
            float T0 = t_span[t], T1 = t_span[t + 1];
            float dt = T1 - T0;
            float tm = T0 + 0.5f * dt;
            s->tst[0] = T0; s->tst[1] = tm; s->tst[2] = tm; s->tst[3] = T1;
            float w14 = dt * (1.0f / 6.0f), w23 = dt * (1.0f / 3.0f);
            s->wgt[0] = w14; s->wgt[1] = w23; s->wgt[2] = w23; s->wgt[3] = w14;
            s->cnx[0] = 0.5f * dt; s->cnx[1] = 0.5f * dt; s->cnx[2] = dt; s->cnx[3] = 0.0f;
        }
        if (tid < ROWS) {
            size_t ri = (size_t)(base + tid) * T_DIM + t;
            float M0 = meal[ri], M1 = meal[ri + 1];
            float V0 = tvns[ri], V1 = tvns[ri + 1];
            s->mv[0][0][tid] = M0; s->mv[0][1][tid] = 0.5f * (M0 + M1); s->mv[0][2][tid] = M1;
            s->mv[1][0][tid] = V0; s->mv[1][1][tid] = 0.5f * (V0 + V1); s->mv[1][2][tid] = V1;
        }
        __syncthreads();

        #pragma unroll 1
        for (int st = 0; st < 4; ++st) {
            const int ph = (st + 1) >> 1;
            const float ts = s->tst[st];
            const float* ms = s->mv[0][ph];
            const float* vs = s->mv[1][ph];

            // ---- input layer ----
            #pragma unroll
            for (int it = 0; it < (ROWS * H_DIM) / NTHREADS; ++it) {
                int idx = tid + it * NTHREADS;
                int r = idx >> 7, j = idx & (H_DIM - 1);
                const float* yr = s->ycur[r];
                float a = s->b_in[j]
                        + ts    * s->W_in[0][j]
                        + yr[0] * s->W_in[1][j]
                        + yr[1] * s->W_in[2][j]
                        + yr[2] * s->W_in[3][j]
                        + yr[3] * s->W_in[4][j]
                        + yr[4] * s->W_in[5][j]
                        + yr[5] * s->W_in[6][j]
                        + yr[3] * s->W_in[7][j]
                        + vs[r] * s->W_in[8][j];
                s->h[0][r][HSWZ(j)] = tanhf(a);
            }
            __syncthreads();

            // ---- 3 hidden layers ----
            #pragma unroll 1
            for (int L = 0; L < 3; ++L) {
                const float* hin  = &s->h[L & 1][0][0];
                float*       hout = &s->h[(L & 1) ^ 1][0][0];
                const float* Wl   = &s->W_h[L][0][0][0];

                ull acc[8][2];
                #pragma unroll
                for (int r = 0; r < 8; ++r) { acc[r][0] = 0ull; acc[r][1] = 0ull; }

                #pragma unroll
                for (int j2 = 0; j2 < 4; ++j2) {
                    const float* hbase = hin + hc[j2];
                    ulonglong2 hr_[8];
                    #pragma unroll
                    for (int r = 0; r < 8; ++r)
                        hr_[r] = *reinterpret_cast<const ulonglong2*>(hbase + r * H_DIM);
                    const float* wb = Wl + (2 * j2) * (8 * WPAD) + wofs;
                    ulonglong2 wA = *reinterpret_cast<const ulonglong2*>(wb);
                    ulonglong2 wB = *reinterpret_cast<const ulonglong2*>(wb + 8 * WPAD);
                    #pragma unroll
                    for (int r = 0; r < 8; ++r) {
                        FFMA2(acc[r][0], hr_[r].x, wA.x);
                        FFMA2(acc[r][1], hr_[r].x, wA.y);
                        FFMA2(acc[r][0], hr_[r].y, wB.x);
                        FFMA2(acc[r][1], hr_[r].y, wB.y);
                    }
                }

                // ---- 3-round shfl fold: row kl lands on lanes with this kl ----
                #pragma unroll
                for (int i = 0; i < 4; ++i)
                    #pragma unroll
                    for (int c = 0; c < 2; ++c) {
                        ull rl = __shfl_xor_sync(0xffffffffu, acc[i][c],     16);
                        ull rh = __shfl_xor_sync(0xffffffffu, acc[i + 4][c], 16);
                        acc[i][c] = hi1 ? add2(acc[i + 4][c], rh) : add2(acc[i][c], rl);
                    }
                #pragma unroll
                for (int i = 0; i < 2; ++i)
                    #pragma unroll
                    for (int c = 0; c < 2; ++c) {
                        ull rl = __shfl_xor_sync(0xffffffffu, acc[i][c],     8);
                        ull rh = __shfl_xor_sync(0xffffffffu, acc[i + 2][c], 8);
                        acc[i][c] = hi2 ? add2(acc[i + 2][c], rh) : add2(acc[i][c], rl);
                    }
                #pragma unroll
                for (int c = 0; c < 2; ++c) {
                    ull rl = __shfl_xor_sync(0xffffffffu, acc[0][c], 4);
                    ull rh = __shfl_xor_sync(0xffffffffu, acc[1][c], 4);
                    acc[0][c] = hi3 ? add2(acc[1][c], rh) : add2(acc[0][c], rl);
                }

                float2 bb = *reinterpret_cast<const float2*>(&s->b_h[L][c0]);
                float2 s0 = unpack2(acc[0][0]);
                float2 s1 = unpack2(acc[0][1]);
                float v0 = tanhf(s0.x + s0.y + bb.x);
                float v1 = tanhf(s1.x + s1.y + bb.y);
                *reinterpret_cast<float2*>(&hout[kl * H_DIM + HSWZ(c0)]) = make_float2(v0, v1);
                __syncthreads();
            }

            // ---- output layer + ODE + RK (8 warps, one batch row each) ----
            if (w < ROWS) {
                const float* hr = &s->h[1][w][0];
                float dots[S_DIM];
                #pragma unroll
                for (int o = 0; o < S_DIM; ++o) {
                    float p = hr[sw0] * s->W_out_t[o][lane]
                            + hr[sw1] * s->W_out_t[o][lane + 32]
                            + hr[sw2] * s->W_out_t[o][lane + 64]
                            + hr[sw3] * s->W_out_t[o][lane + 96];
                    #pragma unroll
                    for (int off = 16; off; off >>= 1)
                        p += __shfl_xor_sync(0xffffffffu, p, off);
                    dots[o] = p;
                }
                if (lane == 0) {
                    float yc[S_DIM];
                    #pragma unroll
                    for (int o = 0; o < S_DIM; ++o) yc[o] = s->ycur[w][o];
                    float m   = ms[w];
                    float wg  = s->wgt[st];
                    float cn  = s->cnx[st];
                    #pragma unroll
                    for (int o = 0; o < S_DIM; ++o) {
                        float kv = dots[o] + s->b_out[o] + ode_comp(o, yc, m);
                        float a  = s->acc[w][o] + wg * kv;
                        s->acc[w][o] = a;
                        if (st < 3) {
                            s->ycur[w][o] = s->y[w][o] + cn * kv;
                        } else {
                            s->ycur[w][o] = a;
                            s->y[w][o]    = a;
                            out[(size_t)(base + w) * T_DIM * S_DIM
                                + (size_t)(t + 1) * S_DIM + o] = a;
                        }
                    }
                }
            }
            __syncthreads();
        } // stages
    } // steps
}

extern "C" void kernel_launch(void* const* d_in, const int* in_sizes, int n_in,
                              void* d_out, int out_size) {
    const float* init   = (const float*)d_in[0];
    const float* t_span = (const float*)d_in[1];
    const float* meal   = (const float*)d_in[2];
    const float* tvns   = (const float*)d_in[3];
    const float* W_in   = (const float*)d_in[4];
    const float* b_in   = (const float*)d_in[5];
    const float* W_h    = (const float*)d_in[6];
    const float* b_h    = (const float*)d_in[7];
    const float* W_out  = (const float*)d_in[8];
    const float* b_out  = (const float*)d_in[9];
    float* out = (float*)d_out;

    const size_t smem_bytes = sizeof(Smem);  // ~222 KB
    cudaFuncSetAttribute(hybrid_ode_kernel,
                         cudaFuncAttributeMaxDynamicSharedMemorySize,
                         (int)smem_bytes);

    hybrid_ode_kernel<<<GRID, NTHREADS, smem_bytes>>>(
        init, t_span, meal, tvns, W_in, b_in, W_h, b_h, W_out, b_out, out);
}

// round 4
// speedup vs baseline: 1.2879x; 1.0307x over previous
#include <cuda_runtime.h>

// HybridODENN: B=1024, T=256, H=128, 3 hidden layers, S=6
#define B_DIM 1024
#define T_DIM 256
#define H_DIM 128
#define S_DIM 6
#define ROWS 8
#define GRID (B_DIM / ROWS)      // 128 CTAs
#define NTHREADS 512
#define HSTRIDE 136              // h row stride in floats (544B: spreads rows over banks)

// ODE constants
#define C_A_GI 0.01f
#define C_K_I  0.1f
#define C_RHO  0.05f
#define C_EMAX 2.0f
#define C_EC50 5.0f
#define C_VMAX 1.0f
#define C_KM   100.0f
#define C_KL   0.2f

typedef unsigned long long ull;

#define FFMA2(d, a, b) asm("fma.rn.f32x2 %0, %1, %2, %0;" : "+l"(d) : "l"(a), "l"(b))

__device__ __forceinline__ ull add2(ull a, ull b) {
    ull d; asm("add.rn.f32x2 %0, %1, %2;" : "=l"(d) : "l"(a), "l"(b)); return d;
}
__device__ __forceinline__ float2 unpack2(ull v) {
    float lo, hi;
    asm("mov.b64 {%0, %1}, %2;" : "=f"(lo), "=f"(hi) : "l"(v));
    return make_float2(lo, hi);
}
__device__ __forceinline__ ull dup2f(float x) {
    ull d; asm("mov.b64 %0, {%1, %1};" : "=l"(d) : "f"(x)); return d;
}
// accurate-enough fast tanh: 1 - 2/(e^{2x}+1), ~1e-7 rel err
__device__ __forceinline__ float tanh_fast(float x) {
    float e;
    asm("ex2.approx.f32 %0, %1;" : "=f"(e) : "f"(x * 2.8853900817779268f));
    float r;
    asm("rcp.approx.f32 %0, %1;" : "=f"(r) : "f"(e + 1.0f));
    return fmaf(-2.0f, r, 1.0f);
}
// h column swizzle: chunk ck = c>>2 -> ck ^ (ck>>3), keep (c&3)
__device__ __forceinline__ int hswz(int c) {
    int ck = c >> 2;
    int ckp = ck ^ (ck >> 3);
    return ckp * 4 + (c & 3);
}

struct __align__(16) Smem {
    // W_h[l][k][ g'*4 + (c&3) ], g' = (c>>2) ^ ((k>>3)&15)
    float W_h[3][H_DIM][H_DIM];   // 192 KB
    float W_in[9][H_DIM];
    float W_out_t[S_DIM][H_DIM];
    float b_in[H_DIM];
    float b_h[3][H_DIM];
    float b_out[8];
    float h[2][ROWS * HSTRIDE];   // swizzled cols + padded rows
    float y[ROWS][S_DIM];
    float ycur[ROWS][S_DIM];
    float acc[ROWS][S_DIM];
    float mv[2][3][ROWS];
    float tst[4];
    float wgt[4];
    float cnx[4];
};

__device__ __forceinline__ float ode_comp(int o, const float* y, float m) {
    float G = y[0], I = y[1], N = y[2], L = y[3], GE = y[4], F = y[5];
    switch (o) {
        case 0: return -C_A_GI * I * G + C_RHO * GE;
        case 1: return C_VMAX * G / (C_KM + G) * (1.0f + C_EMAX * L / (C_EC50 + L)) - C_K_I * I;
        case 2: return -C_RHO * N;
        case 3: return C_RHO * GE - C_KL * L;
        case 4: return m - C_RHO * GE;
        default: return -C_A_GI * I * F;
    }
}

__global__ void __launch_bounds__(NTHREADS, 1)
hybrid_ode_kernel(const float* __restrict__ init,
                  const float* __restrict__ t_span,
                  const float* __restrict__ meal,
                  const float* __restrict__ tvns,
                  const float* __restrict__ gW_in,
                  const float* __restrict__ gb_in,
                  const float* __restrict__ gW_h,
                  const float* __restrict__ gb_h,
                  const float* __restrict__ gW_out,
                  const float* __restrict__ gb_out,
                  float* __restrict__ out)
{
    extern __shared__ __align__(16) char smem_raw[];
    Smem* s = reinterpret_cast<Smem*>(smem_raw);

    const int tid  = threadIdx.x;
    const int base = blockIdx.x * ROWS;

    // ---- one-time weight staging (W_h with col-group XOR swizzle) ----
    for (int i = tid; i < 3 * H_DIM * H_DIM; i += NTHREADS) {
        int l = i >> 14;
        int rem = i & 16383;
        int k = rem >> 7, c = rem & 127;
        int gp = (c >> 2) ^ ((k >> 3) & 15);
        s->W_h[l][k][gp * 4 + (c & 3)] = gW_h[i];
    }
    for (int i = tid; i < 9 * H_DIM; i += NTHREADS) (&s->W_in[0][0])[i] = gW_in[i];
    for (int i = tid; i < H_DIM; i += NTHREADS) s->b_in[i] = gb_in[i];
    for (int i = tid; i < 3 * H_DIM; i += NTHREADS) (&s->b_h[0][0])[i] = gb_h[i];
    for (int i = tid; i < H_DIM * S_DIM; i += NTHREADS) {
        int k = i / S_DIM, o = i % S_DIM;
        s->W_out_t[o][k] = gW_out[i];
    }
    if (tid < S_DIM) s->b_out[tid] = gb_out[tid];
    if (tid < ROWS * S_DIM) {
        int r = tid / S_DIM, o = tid % S_DIM;
        float v = init[(base + r) * S_DIM + o];
        s->y[r][o] = v; s->ycur[r][o] = v; s->acc[r][o] = v;
        out[(size_t)(base + r) * T_DIM * S_DIM + o] = v;
    }
    __syncthreads();

    // ---- GEMM mapping: warp w -> cols [w*8, w*8+8); lane: ks = k-slice, cg = col-group ----
    const int w    = tid >> 5;
    const int lane = tid & 31;
    const int ks   = lane & 15;          // k in [ks*8, ks*8+8)
    const int cg   = lane >> 4;          // 0/1
    const int c0   = w * 8 + cg * 4;     // 4 cols per lane in mainloop
    const int gexp = (((w << 1) + cg) ^ ks) << 2;   // swizzled W col-group offset (floats)
    // h chunk offsets for the two 4-k chunks
    int hco[2];
    #pragma unroll
    for (int kc = 0; kc < 2; ++kc) {
        int ck = 2 * ks + kc;
        hco[kc] = (ck ^ (ck >> 3)) * 4;
    }
    // fold output position: row + col-pair this lane ends up owning
    const int frow = ((ks >> 3) & 1) * 4 + ((ks >> 2) & 1) * 2 + ((ks >> 1) & 1);
    const int fcol = c0 + 2 * (ks & 1);
    const int fco  = frow * HSTRIDE + hswz(fcol);
    const bool b3 = (ks & 8) != 0, b2 = (ks & 4) != 0, b1 = (ks & 2) != 0, b0 = (ks & 1) != 0;
    // epilogue swizzled indices
    const int sw0 = hswz(lane), sw1 = hswz(lane + 32), sw2 = hswz(lane + 64), sw3 = hswz(lane + 96);

    for (int t = 0; t < T_DIM - 1; ++t) {
        if (tid == 0) {
            float T0 = t_span[t], T1 = t_span[t + 1];
            float dt = T1 - T0;
            float tm = T0 + 0.5f * dt;
            s->tst[0] = T0; s->tst[1] = tm; s->tst[2] = tm; s->tst[3] = T1;
            float w14 = dt * (1.0f / 6.0f), w23 = dt * (1.0f / 3.0f);
            s->wgt[0] = w14; s->wgt[1] = w23; s->wgt[2] = w23; s->wgt[3] = w14;
            s->cnx[0] = 0.5f * dt; s->cnx[1] = 0.5f * dt; s->cnx[2] = dt; s->cnx[3] = 0.0f;
        }
        if (tid < ROWS) {
            size_t ri = (size_t)(base + tid) * T_DIM + t;
            float M0 = meal[ri], M1 = meal[ri + 1];
            float V0 = tvns[ri], V1 = tvns[ri + 1];
            s->mv[0][0][tid] = M0; s->mv[0][1][tid] = 0.5f * (M0 + M1); s->mv[0][2][tid] = M1;
            s->mv[1][0][tid] = V0; s->mv[1][1][tid] = 0.5f * (V0 + V1); s->mv[1][2][tid] = V1;
        }
        __syncthreads();

        #pragma unroll 1
        for (int st = 0; st < 4; ++st) {
            const int ph = (st + 1) >> 1;
            const float ts = s->tst[st];
            const float* ms = s->mv[0][ph];
            const float* vs = s->mv[1][ph];

            // ---- input layer: x = [t, y(6), y3, v] -> h[0] ----
            #pragma unroll
            for (int it = 0; it < (ROWS * H_DIM) / NTHREADS; ++it) {
                int idx = tid + it * NTHREADS;
                int r = idx >> 7, j = idx & (H_DIM - 1);
                const float* yr = s->ycur[r];
                float a = s->b_in[j]
                        + ts    * s->W_in[0][j]
                        + yr[0] * s->W_in[1][j]
                        + yr[1] * s->W_in[2][j]
                        + yr[2] * s->W_in[3][j]
                        + yr[3] * s->W_in[4][j]
                        + yr[4] * s->W_in[5][j]
                        + yr[5] * s->W_in[6][j]
                        + yr[3] * s->W_in[7][j]
                        + vs[r] * s->W_in[8][j];
                s->h[0][r * HSTRIDE + hswz(j)] = tanh_fast(a);
            }
            __syncthreads();

            // ---- 3 hidden layers: R8 x C4 x K8 col-packed FFMA2 ----
            #pragma unroll 1
            for (int L = 0; L < 3; ++L) {
                const float* hin  = s->h[L & 1];
                float*       hout = s->h[(L & 1) ^ 1];
                const float* wbase = &s->W_h[L][ks * 8][0] + gexp;

                ull acc[8][2];
                #pragma unroll
                for (int r = 0; r < 8; ++r) { acc[r][0] = 0ull; acc[r][1] = 0ull; }

                #pragma unroll
                for (int kc = 0; kc < 2; ++kc) {
                    ulonglong2 wv[4];
                    #pragma unroll
                    for (int i = 0; i < 4; ++i)
                        wv[i] = *reinterpret_cast<const ulonglong2*>(wbase + (kc * 4 + i) * H_DIM);
                    float4 hv[8];
                    const float* hb = hin + hco[kc];
                    #pragma unroll
                    for (int r = 0; r < 8; ++r)
                        hv[r] = *reinterpret_cast<const float4*>(hb + r * HSTRIDE);
                    #pragma unroll
                    for (int r = 0; r < 8; ++r) {
                        ull d0 = dup2f(hv[r].x), d1 = dup2f(hv[r].y);
                        ull d2 = dup2f(hv[r].z), d3 = dup2f(hv[r].w);
                        FFMA2(acc[r][0], d0, wv[0].x); FFMA2(acc[r][1], d0, wv[0].y);
                        FFMA2(acc[r][0], d1, wv[1].x); FFMA2(acc[r][1], d1, wv[1].y);
                        FFMA2(acc[r][0], d2, wv[2].x); FFMA2(acc[r][1], d2, wv[2].y);
                        FFMA2(acc[r][0], d3, wv[3].x); FFMA2(acc[r][1], d3, wv[3].y);
                    }
                }

                // ---- 4-round send-select fold over 16-way k-split ----
                #pragma unroll
                for (int i = 0; i < 4; ++i)
                    #pragma unroll
                    for (int c = 0; c < 2; ++c) {
                        ull snd = b3 ? acc[i][c] : acc[i + 4][c];
                        ull rcv = __shfl_xor_sync(0xffffffffu, snd, 8);
                        ull kp  = b3 ? acc[i + 4][c] : acc[i][c];
                        acc[i][c] = add2(kp, rcv);
                    }
                #pragma unroll
                for (int i = 0; i < 2; ++i)
                    #pragma unroll
                    for (int c = 0; c < 2; ++c) {
                        ull snd = b2 ? acc[i][c] : acc[i + 2][c];
                        ull rcv = __shfl_xor_sync(0xffffffffu, snd, 4);
                        ull kp  = b2 ? acc[i + 2][c] : acc[i][c];
                        acc[i][c] = add2(kp, rcv);
                    }
                #pragma unroll
                for (int c = 0; c < 2; ++c) {
                    ull snd = b1 ? acc[0][c] : acc[1][c];
                    ull rcv = __shfl_xor_sync(0xffffffffu, snd, 2);
                    ull kp  = b1 ? acc[1][c] : acc[0][c];
                    acc[0][c] = add2(kp, rcv);
                }
                ull fin;
                {
                    ull snd = b0 ? acc[0][0] : acc[0][1];
                    ull rcv = __shfl_xor_sync(0xffffffffu, snd, 1);
                    ull kp  = b0 ? acc[0][1] : acc[0][0];
                    fin = add2(kp, rcv);
                }

                float2 vv = unpack2(fin);
                float2 bb = *reinterpret_cast<const float2*>(&s->b_h[L][fcol]);
                float2 rr;
                rr.x = tanh_fast(vv.x + bb.x);
                rr.y = tanh_fast(vv.y + bb.y);
                *reinterpret_cast<float2*>(&hout[fco]) = rr;
                __syncthreads();
            }

            // ---- output layer + ODE + RK (8 warps, one batch row each) ----
            if (w < ROWS) {
                const float* hr = &s->h[1][w * HSTRIDE];
                float dots[S_DIM];
                #pragma unroll
                for (int o = 0; o < S_DIM; ++o) {
                    float p = hr[sw0] * s->W_out_t[o][lane]
                            + hr[sw1] * s->W_out_t[o][lane + 32]
                            + hr[sw2] * s->W_out_t[o][lane + 64]
                            + hr[sw3] * s->W_out_t[o][lane + 96];
                    #pragma unroll
                    for (int off = 16; off; off >>= 1)
                        p += __shfl_xor_sync(0xffffffffu, p, off);
                    dots[o] = p;
                }
                if (lane == 0) {
                    float yc[S_DIM];
                    #pragma unroll
                    for (int o = 0; o < S_DIM; ++o) yc[o] = s->ycur[w][o];
                    float m   = ms[w];
                    float wg  = s->wgt[st];
                    float cn  = s->cnx[st];
                    #pragma unroll
                    for (int o = 0; o < S_DIM; ++o) {
                        float kv = dots[o] + s->b_out[o] + ode_comp(o, yc, m);
                        float a  = s->acc[w][o] + wg * kv;
                        s->acc[w][o] = a;
                        if (st < 3) {
                            s->ycur[w][o] = s->y[w][o] + cn * kv;
                        } else {
                            s->ycur[w][o] = a;
                            s->y[w][o]    = a;
                            out[(size_t)(base + w) * T_DIM * S_DIM
                                + (size_t)(t + 1) * S_DIM + o] = a;
                        }
                    }
                }
            }
            __syncthreads();
        } // stages
    } // steps
}

extern "C" void kernel_launch(void* const* d_in, const int* in_sizes, int n_in,
                              void* d_out, int out_size) {
    const float* init   = (const float*)d_in[0];
    const float* t_span = (const float*)d_in[1];
    const float* meal   = (const float*)d_in[2];
    const float* tvns   = (const float*)d_in[3];
    const float* W_in   = (const float*)d_in[4];
    const float* b_in   = (const float*)d_in[5];
    const float* W_h    = (const float*)d_in[6];
    const float* b_h    = (const float*)d_in[7];
    const float* W_out  = (const float*)d_in[8];
    const float* b_out  = (const float*)d_in[9];
    float* out = (float*)d_out;

    const size_t smem_bytes = sizeof(Smem);  // ~211 KB
    cudaFuncSetAttribute(hybrid_ode_kernel,
                         cudaFuncAttributeMaxDynamicSharedMemorySize,
                         (int)smem_bytes);

    hybrid_ode_kernel<<<GRID, NTHREADS, smem_bytes>>>(
        init, t_span, meal, tvns, W_in, b_in, W_h, b_h, W_out, b_out, out);
}